// round 11
// baseline (speedup 1.0000x reference)
#include <cuda_runtime.h>
#include <cuda_fp16.h>
#include <math.h>
#include <stdint.h>

// Problem constants
#define Bn   128
#define Un   2048
#define Kn   2
#define Nn   4
#define Ln   512
#define UK   (Un / Kn)        // 1024
#define UN   (Un / Nn)        // 512
#define XHW  (3 * UK)         // 3072
#define KD   (Kn * XHW)       // 6144
#define OW   (4 * Un)         // 8192
#define NW   (4 * UN)         // 2048

// Output layout
#define XOUT_OFF 0
#define HOUT_OFF (Bn * 2 * Un)
#define COUT_OFF (Bn * 3 * Un)
#define CTX_OFF  (Bn * 4 * Un)

// Scratch
__device__ __half g_xh_hi[Bn * KD];      // fp16 A
__device__ float g_part[Bn * OW];        // ifgo
__device__ float g_score[Bn * Ln];

__device__ __forceinline__ float sigmoidf(float v) {
    return 1.0f / (1.0f + expf(-v));
}

__device__ __forceinline__ uint32_t smem_u32(const void* p) {
    uint32_t a;
    asm("{ .reg .u64 t; cvta.to.shared.u64 t, %1; cvt.u32.u64 %0, t; }"
        : "=r"(a) : "l"(p));
    return a;
}

#define CP16(dst, src) \
    asm volatile("cp.async.cg.shared.global [%0], [%1], 16;" \
        :: "r"(dst), "l"(src))
#define CP_COMMIT() asm volatile("cp.async.commit_group;" ::: "memory")
#define CP_WAIT3()  asm volatile("cp.async.wait_group 3;" ::: "memory")
#define CP_WAIT2()  asm volatile("cp.async.wait_group 2;" ::: "memory")
#define CP_WAIT1()  asm volatile("cp.async.wait_group 1;" ::: "memory")
#define CP_WAIT0()  asm volatile("cp.async.wait_group 0;" ::: "memory")

#define LDSM(r, a) \
    asm volatile("ldmatrix.sync.aligned.m8n8.x4.shared.b16 {%0,%1,%2,%3}, [%4];" \
        : "=r"((r)[0]), "=r"((r)[1]), "=r"((r)[2]), "=r"((r)[3]) : "r"(a))
#define LDSM_T(r, a) \
    asm volatile("ldmatrix.sync.aligned.m8n8.x4.trans.shared.b16 {%0,%1,%2,%3}, [%4];" \
        : "=r"((r)[0]), "=r"((r)[1]), "=r"((r)[2]), "=r"((r)[3]) : "r"(a))

__device__ __forceinline__ void mma_fp16(float* d, const uint32_t* a,
                                         uint32_t b0, uint32_t b1) {
    asm volatile(
        "mma.sync.aligned.m16n8k16.row.col.f32.f16.f16.f32 "
        "{%0,%1,%2,%3}, {%4,%5,%6,%7}, {%8,%9}, {%0,%1,%2,%3};\n"
        : "+f"(d[0]), "+f"(d[1]), "+f"(d[2]), "+f"(d[3])
        : "r"(a[0]), "r"(a[1]), "r"(a[2]), "r"(a[3]), "r"(b0), "r"(b1));
}

__device__ __forceinline__ uint32_t pack_h2(__half a, __half b) {
    uint32_t p;
    asm("mov.b32 %0, {%1, %2};" : "=r"(p)
        : "h"(__half_as_ushort(a)), "h"(__half_as_ushort(b)));
    return p;
}

// ---------------------------------------------------------------------------
// 1) Pack XH as fp16
// ---------------------------------------------------------------------------
__global__ void pack_xh_kernel(const float* __restrict__ x,
                               const float* __restrict__ h,
                               const float* __restrict__ ctx) {
    int idx = blockIdx.x * blockDim.x + threadIdx.x;
    if (idx >= Bn * KD) return;
    int b  = idx / KD;
    int kd = idx - b * KD;
    int k  = kd / XHW;
    int d  = kd - k * XHW;
    int off = b * Un + k * UK;
    float v;
    if (d < UK)            v = h[off + d];
    else if (d < 2 * UK)   v = x[off + d - UK];
    else                   v = ctx[off + d - 2 * UK];
    g_xh_hi[idx] = __float2half_rn(v);
}

// ---------------------------------------------------------------------------
// 2) fp16 GEMM on mma.sync.m16n8k16, single term.
//    A: cp.async, 4 stages in flight (5-buffer ring).
//    W: fp32 LDG with 4-deep register FIFO -> in-register cvt -> STS fp16
//       one stage ahead of compute (MLP=4 on the W path, no pre-convert pass).
//    Per CTA: M=128, N=64, K=6144. BK=32, 512 threads (16 warps: 8 M x 2 N).
// ---------------------------------------------------------------------------
#define BNC   64
#define BKS   32
#define NST   (KD / BKS)             // 192
#define NBUF  5
#define A_STRIDE 80                  // bytes per A row (32 fp16 + pad)
#define ASZb  (128 * A_STRIDE)       // 10240
#define B_STRIDE 144                 // bytes per B k-row (64 fp16 + pad)
#define BSZb  (BKS * B_STRIDE)       // 4608
#define ST_AH 0
#define ST_BH ASZb
#define STSZ  (ASZb + BSZb)          // 14848
#define GSMEM (NBUF * STSZ)          // 74240

__global__ void __launch_bounds__(512, 1)
gemm_fp16_kernel(const float* __restrict__ W) {
    extern __shared__ char smem[];
    const uint32_t sb = smem_u32(smem);
    const int tid  = threadIdx.x;
    const int lane = tid & 31;
    const int warp = tid >> 5;
    const int wm   = warp & 7;        // rows wm*16
    const int wn   = warp >> 3;       // cols wn*32

    const int col0 = blockIdx.x * BNC;
    const int n    = col0 >> 11;
    const int f0   = col0 & (NW - 1);

    float accm[4][4];
#pragma unroll
    for (int j = 0; j < 4; ++j)
#pragma unroll
        for (int q = 0; q < 4; ++q) accm[j][q] = 0.f;

    // A-load mapping: thread -> (row ar, 16B chunk ac); 1 CP16
    const int ar = tid >> 2;          // 0..127
    const int ac = tid & 3;           // 0..3
    // W-load mapping: thread -> (k-row wr, float col wcf); 1 float4 LDG
    const int wr  = tid >> 4;         // 0..31
    const int wcf = (tid & 15) * 4;   // 0..60

    auto loadW = [&](int s) -> float4 {
        const int k0 = s * BKS;
        const int kc = (k0 >= XHW) ? 1 : 0;
        const int d  = k0 - kc * XHW + wr;
        const float* src = W + ((size_t)(kc * Nn + n) * XHW + d) * (size_t)NW + f0 + wcf;
        return *reinterpret_cast<const float4*>(src);
    };

    auto storeW = [&](int s, float4 v0) {
        char* st = smem + (s % NBUF) * STSZ;
        *reinterpret_cast<uint2*>(st + ST_BH + wr * B_STRIDE + wcf * 2) =
            make_uint2(pack_h2(__float2half_rn(v0.x), __float2half_rn(v0.y)),
                       pack_h2(__float2half_rn(v0.z), __float2half_rn(v0.w)));
    };

    auto issueA = [&](int s) {
        const uint32_t stb = sb + (s % NBUF) * STSZ;
        const __half* sh = g_xh_hi + (size_t)ar * KD + s * BKS + ac * 8;
        CP16(stb + ST_AH + ar * A_STRIDE + ac * 16, sh);
    };

    auto compute = [&](int s) {
        const uint32_t stb = sb + (s % NBUF) * STSZ;
#pragma unroll
        for (int ks = 0; ks < 2; ++ks) {
            uint32_t bh[2][4];
#pragma unroll
            for (int t = 0; t < 2; ++t) {
                uint32_t ba = stb + ST_BH + (ks * 16 + (lane & 15)) * B_STRIDE
                            + (wn * 32 + t * 16) * 2 + (lane >> 4) * 16;
                LDSM_T(bh[t], ba);
            }
            uint32_t ah[4];
            uint32_t aa = stb + ST_AH
                        + (wm * 16 + (lane & 15)) * A_STRIDE
                        + ks * 32 + (lane >> 4) * 16;
            LDSM(ah, aa);
#pragma unroll
            for (int nt = 0; nt < 4; ++nt) {
                int t = nt >> 1, g = (nt & 1) * 2;
                mma_fp16(accm[nt], ah, bh[t][g], bh[t][g + 1]);
            }
        }
    };

    // Prologue: 4 A-stages in flight, 4 W-stages in register FIFO
    float4 wreg[4];
#pragma unroll
    for (int i = 0; i < 4; ++i) {
        wreg[i] = loadW(i);
        issueA(i);
        CP_COMMIT();
    }
    storeW(0, wreg[0]);               // B tile for stage 0 (visible after sync)

    for (int s = 0; s < NST; ++s) {
        // A group for stage s complete
        if (s <= NST - 4)      CP_WAIT3();
        else if (s == NST - 3) CP_WAIT2();
        else if (s == NST - 2) CP_WAIT1();
        else                   CP_WAIT0();
        __syncthreads();
        if (s + 4 < NST) {
            wreg[s & 3] = loadW(s + 4);   // LDG 4 stages ahead (slot just freed)
            issueA(s + 4);
            CP_COMMIT();
        }
        if (s + 1 < NST)
            storeW(s + 1, wreg[(s + 1) & 3]);  // cvt+STS one stage ahead
        compute(s);
    }

    // Epilogue
#pragma unroll
    for (int nt = 0; nt < 4; ++nt) {
        int r  = wm * 16 + (lane >> 2);
        int gc = col0 + wn * 32 + nt * 8 + (lane & 3) * 2;
        *reinterpret_cast<float2*>(&g_part[(size_t)r * OW + gc]) =
            make_float2(accm[nt][0], accm[nt][1]);
        *reinterpret_cast<float2*>(&g_part[(size_t)(r + 8) * OW + gc]) =
            make_float2(accm[nt][2], accm[nt][3]);
    }
}

// ---------------------------------------------------------------------------
// 3) Gates + cell update + output concat
// ---------------------------------------------------------------------------
__global__ void gates_kernel(const float* __restrict__ c,
                             const float* __restrict__ ctx,
                             float* __restrict__ out) {
    int idx = blockIdx.x * blockDim.x + threadIdx.x;
    if (idx >= Bn * Un) return;
    int b = idx >> 11;
    int u = idx & (Un - 1);
    int n = u >> 9;
    int j = u & (UN - 1);
    const float* p = g_part + (size_t)b * OW + n * NW + j;
    float iv = sigmoidf(p[0]);
    float fv = sigmoidf(p[512]);
    float gv = tanhf(p[1024]);
    float ov = sigmoidf(p[1536]);
    float cv = c[idx];
    float nc = fv * cv + iv * gv;
    float nh = ov * tanhf(nc);
    out[HOUT_OFF + idx] = nh;
    out[COUT_OFF + idx] = nc;
    out[XOUT_OFF + b * (2 * Un) + u]      = nh;
    out[XOUT_OFF + b * (2 * Un) + Un + u] = ctx[idx];
}

// ---------------------------------------------------------------------------
// 4a) Attention scores
// ---------------------------------------------------------------------------
__global__ void __launch_bounds__(256)
scores_kernel(const float* __restrict__ enc_attn,
              const float* __restrict__ out) {
    __shared__ float sh[Un];
    const int b   = blockIdx.x;
    const int lc  = blockIdx.y;
    const int tid = threadIdx.x;
    const int lane = tid & 31;
    const int warp = tid >> 5;

    const float4* hb = reinterpret_cast<const float4*>(out + HOUT_OFF + (size_t)b * Un);
    reinterpret_cast<float4*>(sh)[tid]       = hb[tid];
    reinterpret_cast<float4*>(sh)[tid + 256] = hb[tid + 256];
    __syncthreads();

    const float4* sh4 = reinterpret_cast<const float4*>(sh);
    const float* ea = enc_attn + (size_t)b * Ln * Un;
#pragma unroll 1
    for (int i = 0; i < 16; ++i) {
        int l = lc * 128 + warp * 16 + i;
        const float4* row = reinterpret_cast<const float4*>(ea + (size_t)l * Un);
        float s = 0.0f;
#pragma unroll 4
        for (int it = lane; it < Un / 4; it += 32) {
            float4 v = row[it];
            float4 hv = sh4[it];
            s += v.x * hv.x + v.y * hv.y + v.z * hv.z + v.w * hv.w;
        }
#pragma unroll
        for (int o = 16; o > 0; o >>= 1)
            s += __shfl_xor_sync(0xffffffffu, s, o);
        if (lane == 0) g_score[b * Ln + l] = s;
    }
}

// ---------------------------------------------------------------------------
// 4b) Softmax
// ---------------------------------------------------------------------------
__global__ void __launch_bounds__(512)
softmax_kernel() {
    __shared__ float red[16];
    __shared__ float red1;
    const int b = blockIdx.x;
    const int tid = threadIdx.x;
    const int lane = tid & 31;
    const int warp = tid >> 5;

    float v = g_score[b * Ln + tid];
    float m = v;
#pragma unroll
    for (int o = 16; o > 0; o >>= 1)
        m = fmaxf(m, __shfl_xor_sync(0xffffffffu, m, o));
    if (lane == 0) red[warp] = m;
    __syncthreads();
    if (tid == 0) {
        float mm = red[0];
#pragma unroll
        for (int i = 1; i < 16; ++i) mm = fmaxf(mm, red[i]);
        red1 = mm;
    }
    __syncthreads();
    float e = expf(v - red1);
    float s = e;
#pragma unroll
    for (int o = 16; o > 0; o >>= 1)
        s += __shfl_xor_sync(0xffffffffu, s, o);
    if (lane == 0) red[warp] = s;
    __syncthreads();
    if (tid == 0) {
        float ss = 0.0f;
#pragma unroll
        for (int i = 0; i < 16; ++i) ss += red[i];
        red1 = ss;
    }
    __syncthreads();
    g_score[b * Ln + tid] = e / red1;
}

// ---------------------------------------------------------------------------
// 4c) Weighted sum
// ---------------------------------------------------------------------------
__global__ void __launch_bounds__(128)
ctx_kernel(const float* __restrict__ enc_out,
           float* __restrict__ out) {
    __shared__ float w[Ln];
    const int b   = blockIdx.x;
    const int uc  = blockIdx.y;
    const int tid = threadIdx.x;

    reinterpret_cast<float4*>(w)[tid] =
        reinterpret_cast<const float4*>(g_score + (size_t)b * Ln)[tid];
    __syncthreads();

    const float* eo = enc_out + (size_t)b * Ln * Un + uc * 512 + tid * 4;
    float4 acc = make_float4(0.f, 0.f, 0.f, 0.f);
#pragma unroll 4
    for (int l = 0; l < Ln; ++l) {
        float ww = w[l];
        float4 vv = *reinterpret_cast<const float4*>(eo + (size_t)l * Un);
        acc.x = fmaf(ww, vv.x, acc.x);
        acc.y = fmaf(ww, vv.y, acc.y);
        acc.z = fmaf(ww, vv.z, acc.z);
        acc.w = fmaf(ww, vv.w, acc.w);
    }
    *reinterpret_cast<float4*>(out + CTX_OFF + (size_t)b * Un + uc * 512 + tid * 4) = acc;
}

// ---------------------------------------------------------------------------
extern "C" void kernel_launch(void* const* d_in, const int* in_sizes, int n_in,
                              void* d_out, int out_size) {
    const float* x        = (const float*)d_in[0];
    const float* h        = (const float*)d_in[1];
    const float* c        = (const float*)d_in[2];
    const float* context  = (const float*)d_in[3];
    const float* W        = (const float*)d_in[4];
    const float* enc_attn = (const float*)d_in[5];
    const float* enc_out  = (const float*)d_in[6];
    float* out = (float*)d_out;

    cudaFuncSetAttribute(gemm_fp16_kernel,
                         cudaFuncAttributeMaxDynamicSharedMemorySize, GSMEM);

    pack_xh_kernel<<<(Bn * KD + 255) / 256, 256>>>(x, h, context);
    gemm_fp16_kernel<<<OW / BNC, 512, GSMEM>>>(W);
    gates_kernel<<<(Bn * Un + 255) / 256, 256>>>(c, context, out);
    scores_kernel<<<dim3(Bn, 4), 256>>>(enc_attn, out);
    softmax_kernel<<<Bn, 512>>>();
    ctx_kernel<<<dim3(Bn, 4), 128>>>(enc_out, out);
}

// round 13
// speedup vs baseline: 1.2001x; 1.2001x over previous
#include <cuda_runtime.h>
#include <cuda_fp16.h>
#include <math.h>
#include <stdint.h>

// Problem constants
#define Bn   128
#define Un   2048
#define Kn   2
#define Nn   4
#define Ln   512
#define UK   (Un / Kn)        // 1024
#define UN   (Un / Nn)        // 512
#define XHW  (3 * UK)         // 3072
#define KD   (Kn * XHW)       // 6144
#define OW   (4 * Un)         // 8192
#define NW   (4 * UN)         // 2048

// Output layout
#define XOUT_OFF 0
#define HOUT_OFF (Bn * 2 * Un)
#define COUT_OFF (Bn * 3 * Un)
#define CTX_OFF  (Bn * 4 * Un)

// Scratch
__device__ __half g_xh_hi[Bn * KD];       // fp16 A
__device__ __half g_whi[(size_t)KD * OW]; // fp16 W (100 MB)
__device__ float g_part[Bn * OW];         // ifgo
__device__ float g_score[Bn * Ln];

__device__ __forceinline__ float sigmoidf(float v) {
    return 1.0f / (1.0f + expf(-v));
}

__device__ __forceinline__ uint32_t smem_u32(const void* p) {
    uint32_t a;
    asm("{ .reg .u64 t; cvta.to.shared.u64 t, %1; cvt.u32.u64 %0, t; }"
        : "=r"(a) : "l"(p));
    return a;
}

#define CP16(dst, src) \
    asm volatile("cp.async.cg.shared.global [%0], [%1], 16;" \
        :: "r"(dst), "l"(src))
#define CP_COMMIT() asm volatile("cp.async.commit_group;" ::: "memory")
#define CP_WAIT3()  asm volatile("cp.async.wait_group 3;" ::: "memory")
#define CP_WAIT2()  asm volatile("cp.async.wait_group 2;" ::: "memory")
#define CP_WAIT1()  asm volatile("cp.async.wait_group 1;" ::: "memory")
#define CP_WAIT0()  asm volatile("cp.async.wait_group 0;" ::: "memory")

#define LDSM(r, a) \
    asm volatile("ldmatrix.sync.aligned.m8n8.x4.shared.b16 {%0,%1,%2,%3}, [%4];" \
        : "=r"((r)[0]), "=r"((r)[1]), "=r"((r)[2]), "=r"((r)[3]) : "r"(a))
#define LDSM_T(r, a) \
    asm volatile("ldmatrix.sync.aligned.m8n8.x4.trans.shared.b16 {%0,%1,%2,%3}, [%4];" \
        : "=r"((r)[0]), "=r"((r)[1]), "=r"((r)[2]), "=r"((r)[3]) : "r"(a))

__device__ __forceinline__ void mma_fp16(float* d, const uint32_t* a,
                                         uint32_t b0, uint32_t b1) {
    asm volatile(
        "mma.sync.aligned.m16n8k16.row.col.f32.f16.f16.f32 "
        "{%0,%1,%2,%3}, {%4,%5,%6,%7}, {%8,%9}, {%0,%1,%2,%3};\n"
        : "+f"(d[0]), "+f"(d[1]), "+f"(d[2]), "+f"(d[3])
        : "r"(a[0]), "r"(a[1]), "r"(a[2]), "r"(a[3]), "r"(b0), "r"(b1));
}

__device__ __forceinline__ uint32_t pack_h2(__half a, __half b) {
    uint32_t p;
    asm("mov.b32 %0, {%1, %2};" : "=r"(p)
        : "h"(__half_as_ushort(a)), "h"(__half_as_ushort(b)));
    return p;
}

// ---------------------------------------------------------------------------
// 0) Convert W fp32 -> fp16 (flat elementwise, coalesced)
// ---------------------------------------------------------------------------
__global__ void __launch_bounds__(256)
convw_kernel(const float* __restrict__ W) {
    size_t i = ((size_t)blockIdx.x * 256 + threadIdx.x) * 4;
    float4 v = *reinterpret_cast<const float4*>(W + i);
    uint2 o;
    o.x = pack_h2(__float2half_rn(v.x), __float2half_rn(v.y));
    o.y = pack_h2(__float2half_rn(v.z), __float2half_rn(v.w));
    *reinterpret_cast<uint2*>(g_whi + i) = o;
}

// ---------------------------------------------------------------------------
// 1) Pack XH as fp16
// ---------------------------------------------------------------------------
__global__ void pack_xh_kernel(const float* __restrict__ x,
                               const float* __restrict__ h,
                               const float* __restrict__ ctx) {
    int idx = blockIdx.x * blockDim.x + threadIdx.x;
    if (idx >= Bn * KD) return;
    int b  = idx / KD;
    int kd = idx - b * KD;
    int k  = kd / XHW;
    int d  = kd - k * XHW;
    int off = b * Un + k * UK;
    float v;
    if (d < UK)            v = h[off + d];
    else if (d < 2 * UK)   v = x[off + d - UK];
    else                   v = ctx[off + d - 2 * UK];
    g_xh_hi[idx] = __float2half_rn(v);
}

// ---------------------------------------------------------------------------
// 2) fp16 single-term GEMM, all-cp.async, 5-buffer ring, 4 stages in flight.
//    Per CTA: M=128, N=64, K=6144. BK=32, 512 threads (16 warps: 8 M x 2 N).
// ---------------------------------------------------------------------------
#define BNC   64
#define BKS   32
#define NST   (KD / BKS)             // 192
#define NBUF  5
#define A_STRIDE 80                  // bytes per A row (32 fp16 + pad)
#define ASZb  (128 * A_STRIDE)       // 10240
#define B_STRIDE 144                 // bytes per B k-row (64 fp16 + pad)
#define BSZb  (BKS * B_STRIDE)       // 4608
#define ST_AH 0
#define ST_BH ASZb
#define STSZ  (ASZb + BSZb)          // 14848
#define GSMEM (NBUF * STSZ)          // 74240

__global__ void __launch_bounds__(512, 1)
gemm_fp16_kernel() {
    extern __shared__ char smem[];
    const uint32_t sb = smem_u32(smem);
    const int tid  = threadIdx.x;
    const int lane = tid & 31;
    const int warp = tid >> 5;
    const int wm   = warp & 7;        // rows wm*16
    const int wn   = warp >> 3;       // cols wn*32

    const int col0 = blockIdx.x * BNC;
    const int n    = col0 >> 11;
    const int f0   = col0 & (NW - 1);

    float accm[4][4];
#pragma unroll
    for (int j = 0; j < 4; ++j)
#pragma unroll
        for (int q = 0; q < 4; ++q) accm[j][q] = 0.f;

    // A-load mapping: thread -> (row ar, 16B chunk ac); 1 CP16
    const int ar = tid >> 2;          // 0..127
    const int ac = tid & 3;           // 0..3
    // B-load mapping: threads 0..255 -> (k-row br, 16B chunk bc); 1 CP16
    const int br = tid >> 3;          // only tid<256 used -> 0..31
    const int bc = tid & 7;           // 0..7

    auto issue = [&](int s) {
        const uint32_t stb = sb + (s % NBUF) * STSZ;
        const int k0 = s * BKS;
        const __half* sh = g_xh_hi + (size_t)ar * KD + k0 + ac * 8;
        CP16(stb + ST_AH + ar * A_STRIDE + ac * 16, sh);
        if (tid < 256) {
            const int kc = (k0 >= XHW) ? 1 : 0;
            const int d  = k0 - kc * XHW + br;
            const __half* wsrc = g_whi + ((size_t)(kc * Nn + n) * XHW + d) * (size_t)NW
                               + f0 + bc * 8;
            CP16(stb + ST_BH + br * B_STRIDE + bc * 16, wsrc);
        }
    };

    auto compute = [&](int s) {
        const uint32_t stb = sb + (s % NBUF) * STSZ;
#pragma unroll
        for (int ks = 0; ks < 2; ++ks) {
            uint32_t bh[2][4];
#pragma unroll
            for (int t = 0; t < 2; ++t) {
                uint32_t ba = stb + ST_BH + (ks * 16 + (lane & 15)) * B_STRIDE
                            + (wn * 32 + t * 16) * 2 + (lane >> 4) * 16;
                LDSM_T(bh[t], ba);
            }
            uint32_t ah[4];
            uint32_t aa = stb + ST_AH
                        + (wm * 16 + (lane & 15)) * A_STRIDE
                        + ks * 32 + (lane >> 4) * 16;
            LDSM(ah, aa);
#pragma unroll
            for (int nt = 0; nt < 4; ++nt) {
                int t = nt >> 1, g = (nt & 1) * 2;
                mma_fp16(accm[nt], ah, bh[t][g], bh[t][g + 1]);
            }
        }
    };

    // Prologue: 4 stages in flight
#pragma unroll
    for (int s = 0; s < 4; ++s) { issue(s); CP_COMMIT(); }

    for (int s = 0; s < NST; ++s) {
        if (s <= NST - 4)      CP_WAIT3();
        else if (s == NST - 3) CP_WAIT2();
        else if (s == NST - 2) CP_WAIT1();
        else                   CP_WAIT0();
        __syncthreads();
        if (s + 4 < NST) { issue(s + 4); CP_COMMIT(); }
        compute(s);
    }

    // Epilogue
#pragma unroll
    for (int nt = 0; nt < 4; ++nt) {
        int r  = wm * 16 + (lane >> 2);
        int gc = col0 + wn * 32 + nt * 8 + (lane & 3) * 2;
        *reinterpret_cast<float2*>(&g_part[(size_t)r * OW + gc]) =
            make_float2(accm[nt][0], accm[nt][1]);
        *reinterpret_cast<float2*>(&g_part[(size_t)(r + 8) * OW + gc]) =
            make_float2(accm[nt][2], accm[nt][3]);
    }
}

// ---------------------------------------------------------------------------
// 3) Gates + cell update + output concat
// ---------------------------------------------------------------------------
__global__ void gates_kernel(const float* __restrict__ c,
                             const float* __restrict__ ctx,
                             float* __restrict__ out) {
    int idx = blockIdx.x * blockDim.x + threadIdx.x;
    if (idx >= Bn * Un) return;
    int b = idx >> 11;
    int u = idx & (Un - 1);
    int n = u >> 9;
    int j = u & (UN - 1);
    const float* p = g_part + (size_t)b * OW + n * NW + j;
    float iv = sigmoidf(p[0]);
    float fv = sigmoidf(p[512]);
    float gv = tanhf(p[1024]);
    float ov = sigmoidf(p[1536]);
    float cv = c[idx];
    float nc = fv * cv + iv * gv;
    float nh = ov * tanhf(nc);
    out[HOUT_OFF + idx] = nh;
    out[COUT_OFF + idx] = nc;
    out[XOUT_OFF + b * (2 * Un) + u]      = nh;
    out[XOUT_OFF + b * (2 * Un) + Un + u] = ctx[idx];
}

// ---------------------------------------------------------------------------
// 4a) Attention scores
// ---------------------------------------------------------------------------
__global__ void __launch_bounds__(256)
scores_kernel(const float* __restrict__ enc_attn,
              const float* __restrict__ out) {
    __shared__ float sh[Un];
    const int b   = blockIdx.x;
    const int lc  = blockIdx.y;
    const int tid = threadIdx.x;
    const int lane = tid & 31;
    const int warp = tid >> 5;

    const float4* hb = reinterpret_cast<const float4*>(out + HOUT_OFF + (size_t)b * Un);
    reinterpret_cast<float4*>(sh)[tid]       = hb[tid];
    reinterpret_cast<float4*>(sh)[tid + 256] = hb[tid + 256];
    __syncthreads();

    const float4* sh4 = reinterpret_cast<const float4*>(sh);
    const float* ea = enc_attn + (size_t)b * Ln * Un;
#pragma unroll 1
    for (int i = 0; i < 16; ++i) {
        int l = lc * 128 + warp * 16 + i;
        const float4* row = reinterpret_cast<const float4*>(ea + (size_t)l * Un);
        float s = 0.0f;
#pragma unroll 4
        for (int it = lane; it < Un / 4; it += 32) {
            float4 v = row[it];
            float4 hv = sh4[it];
            s += v.x * hv.x + v.y * hv.y + v.z * hv.z + v.w * hv.w;
        }
#pragma unroll
        for (int o = 16; o > 0; o >>= 1)
            s += __shfl_xor_sync(0xffffffffu, s, o);
        if (lane == 0) g_score[b * Ln + l] = s;
    }
}

// ---------------------------------------------------------------------------
// 4b) Softmax
// ---------------------------------------------------------------------------
__global__ void __launch_bounds__(512)
softmax_kernel() {
    __shared__ float red[16];
    __shared__ float red1;
    const int b = blockIdx.x;
    const int tid = threadIdx.x;
    const int lane = tid & 31;
    const int warp = tid >> 5;

    float v = g_score[b * Ln + tid];
    float m = v;
#pragma unroll
    for (int o = 16; o > 0; o >>= 1)
        m = fmaxf(m, __shfl_xor_sync(0xffffffffu, m, o));
    if (lane == 0) red[warp] = m;
    __syncthreads();
    if (tid == 0) {
        float mm = red[0];
#pragma unroll
        for (int i = 1; i < 16; ++i) mm = fmaxf(mm, red[i]);
        red1 = mm;
    }
    __syncthreads();
    float e = expf(v - red1);
    float s = e;
#pragma unroll
    for (int o = 16; o > 0; o >>= 1)
        s += __shfl_xor_sync(0xffffffffu, s, o);
    if (lane == 0) red[warp] = s;
    __syncthreads();
    if (tid == 0) {
        float ss = 0.0f;
#pragma unroll
        for (int i = 0; i < 16; ++i) ss += red[i];
        red1 = ss;
    }
    __syncthreads();
    g_score[b * Ln + tid] = e / red1;
}

// ---------------------------------------------------------------------------
// 4c) Weighted sum
// ---------------------------------------------------------------------------
__global__ void __launch_bounds__(128)
ctx_kernel(const float* __restrict__ enc_out,
           float* __restrict__ out) {
    __shared__ float w[Ln];
    const int b   = blockIdx.x;
    const int uc  = blockIdx.y;
    const int tid = threadIdx.x;

    reinterpret_cast<float4*>(w)[tid] =
        reinterpret_cast<const float4*>(g_score + (size_t)b * Ln)[tid];
    __syncthreads();

    const float* eo = enc_out + (size_t)b * Ln * Un + uc * 512 + tid * 4;
    float4 acc = make_float4(0.f, 0.f, 0.f, 0.f);
#pragma unroll 4
    for (int l = 0; l < Ln; ++l) {
        float ww = w[l];
        float4 vv = *reinterpret_cast<const float4*>(eo + (size_t)l * Un);
        acc.x = fmaf(ww, vv.x, acc.x);
        acc.y = fmaf(ww, vv.y, acc.y);
        acc.z = fmaf(ww, vv.z, acc.z);
        acc.w = fmaf(ww, vv.w, acc.w);
    }
    *reinterpret_cast<float4*>(out + CTX_OFF + (size_t)b * Un + uc * 512 + tid * 4) = acc;
}

// ---------------------------------------------------------------------------
extern "C" void kernel_launch(void* const* d_in, const int* in_sizes, int n_in,
                              void* d_out, int out_size) {
    const float* x        = (const float*)d_in[0];
    const float* h        = (const float*)d_in[1];
    const float* c        = (const float*)d_in[2];
    const float* context  = (const float*)d_in[3];
    const float* W        = (const float*)d_in[4];
    const float* enc_attn = (const float*)d_in[5];
    const float* enc_out  = (const float*)d_in[6];
    float* out = (float*)d_out;

    cudaFuncSetAttribute(gemm_fp16_kernel,
                         cudaFuncAttributeMaxDynamicSharedMemorySize, GSMEM);

    convw_kernel<<<(int)(((size_t)KD * OW / 4) / 256), 256>>>(W);
    pack_xh_kernel<<<(Bn * KD + 255) / 256, 256>>>(x, h, context);
    gemm_fp16_kernel<<<OW / BNC, 512, GSMEM>>>();
    gates_kernel<<<(Bn * Un + 255) / 256, 256>>>(c, context, out);
    scores_kernel<<<dim3(Bn, 4), 256>>>(enc_attn, out);
    softmax_kernel<<<Bn, 512>>>();
    ctx_kernel<<<dim3(Bn, 4), 128>>>(enc_out, out);
}

// round 15
// speedup vs baseline: 1.2864x; 1.0719x over previous
#include <cuda_runtime.h>
#include <cuda_fp16.h>
#include <math.h>
#include <stdint.h>

// Problem constants
#define Bn   128
#define Un   2048
#define Kn   2
#define Nn   4
#define Ln   512
#define UK   (Un / Kn)        // 1024
#define UN   (Un / Nn)        // 512
#define XHW  (3 * UK)         // 3072
#define KD   (Kn * XHW)       // 6144
#define OW   (4 * Un)         // 8192
#define NW   (4 * UN)         // 2048

// Output layout
#define XOUT_OFF 0
#define HOUT_OFF (Bn * 2 * Un)
#define COUT_OFF (Bn * 3 * Un)
#define CTX_OFF  (Bn * 4 * Un)

// Scratch
__device__ __half g_xh_hi[Bn * KD];       // fp16 A
__device__ float g_part[Bn * OW];         // ifgo
__device__ float g_score[Bn * Ln];

__device__ __forceinline__ float sigmoidf(float v) {
    return 1.0f / (1.0f + expf(-v));
}

__device__ __forceinline__ uint32_t smem_u32(const void* p) {
    uint32_t a;
    asm("{ .reg .u64 t; cvta.to.shared.u64 t, %1; cvt.u32.u64 %0, t; }"
        : "=r"(a) : "l"(p));
    return a;
}

#define CP16(dst, src) \
    asm volatile("cp.async.cg.shared.global [%0], [%1], 16;" \
        :: "r"(dst), "l"(src))
#define CP_COMMIT() asm volatile("cp.async.commit_group;" ::: "memory")
#define CP_WAIT3()  asm volatile("cp.async.wait_group 3;" ::: "memory")
#define CP_WAIT2()  asm volatile("cp.async.wait_group 2;" ::: "memory")
#define CP_WAIT1()  asm volatile("cp.async.wait_group 1;" ::: "memory")
#define CP_WAIT0()  asm volatile("cp.async.wait_group 0;" ::: "memory")

#define LDSM(r, a) \
    asm volatile("ldmatrix.sync.aligned.m8n8.x4.shared.b16 {%0,%1,%2,%3}, [%4];" \
        : "=r"((r)[0]), "=r"((r)[1]), "=r"((r)[2]), "=r"((r)[3]) : "r"(a))
#define LDSM_T(r, a) \
    asm volatile("ldmatrix.sync.aligned.m8n8.x4.trans.shared.b16 {%0,%1,%2,%3}, [%4];" \
        : "=r"((r)[0]), "=r"((r)[1]), "=r"((r)[2]), "=r"((r)[3]) : "r"(a))

__device__ __forceinline__ void mma_fp16(float* d, const uint32_t* a,
                                         uint32_t b0, uint32_t b1) {
    asm volatile(
        "mma.sync.aligned.m16n8k16.row.col.f32.f16.f16.f32 "
        "{%0,%1,%2,%3}, {%4,%5,%6,%7}, {%8,%9}, {%0,%1,%2,%3};\n"
        : "+f"(d[0]), "+f"(d[1]), "+f"(d[2]), "+f"(d[3])
        : "r"(a[0]), "r"(a[1]), "r"(a[2]), "r"(a[3]), "r"(b0), "r"(b1));
}

__device__ __forceinline__ uint32_t pack_h2(__half a, __half b) {
    uint32_t p;
    asm("mov.b32 %0, {%1, %2};" : "=r"(p)
        : "h"(__half_as_ushort(a)), "h"(__half_as_ushort(b)));
    return p;
}

// ---------------------------------------------------------------------------
// 1) Pack XH as fp16
// ---------------------------------------------------------------------------
__global__ void pack_xh_kernel(const float* __restrict__ x,
                               const float* __restrict__ h,
                               const float* __restrict__ ctx) {
    int idx = blockIdx.x * blockDim.x + threadIdx.x;
    if (idx >= Bn * KD) return;
    int b  = idx / KD;
    int kd = idx - b * KD;
    int k  = kd / XHW;
    int d  = kd - k * XHW;
    int off = b * Un + k * UK;
    float v;
    if (d < UK)            v = h[off + d];
    else if (d < 2 * UK)   v = x[off + d - UK];
    else                   v = ctx[off + d - 2 * UK];
    g_xh_hi[idx] = __float2half_rn(v);
}

// ---------------------------------------------------------------------------
// 2) fp16 single-term GEMM; A fp16 + B fp32 both via cp.async (5-slot ring,
//    4 stages in flight); per-stage in-smem B convert fp32->fp16 into ONE
//    reused fp16 tile (sync1 already orders compute(s-1) before convert(s)).
//    Per CTA: M=128, N=64, K=6144. BK=32, 512 threads (16 warps: 8 M x 2 N).
// ---------------------------------------------------------------------------
#define BNC   64
#define BKS   32
#define NST   (KD / BKS)             // 192
#define NBUF  5
#define A_STRIDE 80                  // bytes per A row (32 fp16 + pad)
#define ASZb  (128 * A_STRIDE)       // 10240
#define BF_STRIDE 272                // bytes per B fp32 k-row (64 fp32 + pad)
#define BFSZb (BKS * BF_STRIDE)      // 8704
#define B_STRIDE 144                 // bytes per B fp16 k-row (64 fp16 + pad)
#define BHSZb (BKS * B_STRIDE)       // 4608
#define ST_AH 0
#define ST_BF ASZb                   // fp32 B within ring slot
#define STSZ  (ASZb + BFSZb)         // 18944
#define BF16_OFF (NBUF * STSZ)       // 94720 (single fp16 B tile)
#define GSMEM (BF16_OFF + BHSZb)     // 99328

__global__ void __launch_bounds__(512, 1)
gemm_fp16_kernel(const float* __restrict__ W) {
    extern __shared__ char smem[];
    const uint32_t sb = smem_u32(smem);
    const int tid  = threadIdx.x;
    const int lane = tid & 31;
    const int warp = tid >> 5;
    const int wm   = warp & 7;        // rows wm*16
    const int wn   = warp >> 3;       // cols wn*32

    const int col0 = blockIdx.x * BNC;
    const int n    = col0 >> 11;
    const int f0   = col0 & (NW - 1);

    float accm[4][4];
#pragma unroll
    for (int j = 0; j < 4; ++j)
#pragma unroll
        for (int q = 0; q < 4; ++q) accm[j][q] = 0.f;

    // A-load mapping: thread -> (row ar, 16B chunk ac); 1 CP16
    const int ar = tid >> 2;          // 0..127
    const int ac = tid & 3;           // 0..3
    // B-load/convert mapping: thread -> (k-row br, 4-float chunk bcf)
    const int br  = tid >> 4;         // 0..31
    const int bcf = (tid & 15) * 4;   // float col 0..60

    auto issue = [&](int s) {
        const uint32_t stb = sb + (s % NBUF) * STSZ;
        const int k0 = s * BKS;
        const __half* sh = g_xh_hi + (size_t)ar * KD + k0 + ac * 8;
        CP16(stb + ST_AH + ar * A_STRIDE + ac * 16, sh);
        const int kc = (k0 >= XHW) ? 1 : 0;
        const int d  = k0 - kc * XHW + br;
        const float* wsrc = W + ((size_t)(kc * Nn + n) * XHW + d) * (size_t)NW
                          + f0 + bcf;
        CP16(stb + ST_BF + br * BF_STRIDE + bcf * 4, wsrc);
    };

    auto convertB = [&](int s) {
        const char* src = smem + (s % NBUF) * STSZ + ST_BF;
        float4 v = *reinterpret_cast<const float4*>(src + br * BF_STRIDE + bcf * 4);
        *reinterpret_cast<uint2*>(smem + BF16_OFF + br * B_STRIDE + bcf * 2) =
            make_uint2(pack_h2(__float2half_rn(v.x), __float2half_rn(v.y)),
                       pack_h2(__float2half_rn(v.z), __float2half_rn(v.w)));
    };

    auto compute = [&](int s) {
        const uint32_t stb = sb + (s % NBUF) * STSZ;
        const uint32_t bft = sb + BF16_OFF;
#pragma unroll
        for (int ks = 0; ks < 2; ++ks) {
            uint32_t bh[2][4];
#pragma unroll
            for (int t = 0; t < 2; ++t) {
                uint32_t ba = bft + (ks * 16 + (lane & 15)) * B_STRIDE
                            + (wn * 32 + t * 16) * 2 + (lane >> 4) * 16;
                LDSM_T(bh[t], ba);
            }
            uint32_t ah[4];
            uint32_t aa = stb + ST_AH
                        + (wm * 16 + (lane & 15)) * A_STRIDE
                        + ks * 32 + (lane >> 4) * 16;
            LDSM(ah, aa);
#pragma unroll
            for (int nt = 0; nt < 4; ++nt) {
                int t = nt >> 1, g = (nt & 1) * 2;
                mma_fp16(accm[nt], ah, bh[t][g], bh[t][g + 1]);
            }
        }
    };

    // Prologue: 4 stages in flight
#pragma unroll
    for (int s = 0; s < 4; ++s) { issue(s); CP_COMMIT(); }

    for (int s = 0; s < NST; ++s) {
        if (s <= NST - 4)      CP_WAIT3();
        else if (s == NST - 3) CP_WAIT2();
        else if (s == NST - 2) CP_WAIT1();
        else                   CP_WAIT0();
        __syncthreads();                       // sync1: data ready + prev compute done
        if (s + 4 < NST) { issue(s + 4); CP_COMMIT(); }
        convertB(s);
        __syncthreads();                       // sync2: fp16 B tile ready
        compute(s);
    }

    // Epilogue
#pragma unroll
    for (int nt = 0; nt < 4; ++nt) {
        int r  = wm * 16 + (lane >> 2);
        int gc = col0 + wn * 32 + nt * 8 + (lane & 3) * 2;
        *reinterpret_cast<float2*>(&g_part[(size_t)r * OW + gc]) =
            make_float2(accm[nt][0], accm[nt][1]);
        *reinterpret_cast<float2*>(&g_part[(size_t)(r + 8) * OW + gc]) =
            make_float2(accm[nt][2], accm[nt][3]);
    }
}

// ---------------------------------------------------------------------------
// 3) Gates + cell update + output concat
// ---------------------------------------------------------------------------
__global__ void gates_kernel(const float* __restrict__ c,
                             const float* __restrict__ ctx,
                             float* __restrict__ out) {
    int idx = blockIdx.x * blockDim.x + threadIdx.x;
    if (idx >= Bn * Un) return;
    int b = idx >> 11;
    int u = idx & (Un - 1);
    int n = u >> 9;
    int j = u & (UN - 1);
    const float* p = g_part + (size_t)b * OW + n * NW + j;
    float iv = sigmoidf(p[0]);
    float fv = sigmoidf(p[512]);
    float gv = tanhf(p[1024]);
    float ov = sigmoidf(p[1536]);
    float cv = c[idx];
    float nc = fv * cv + iv * gv;
    float nh = ov * tanhf(nc);
    out[HOUT_OFF + idx] = nh;
    out[COUT_OFF + idx] = nc;
    out[XOUT_OFF + b * (2 * Un) + u]      = nh;
    out[XOUT_OFF + b * (2 * Un) + Un + u] = ctx[idx];
}

// ---------------------------------------------------------------------------
// 4a) Attention scores
// ---------------------------------------------------------------------------
__global__ void __launch_bounds__(256)
scores_kernel(const float* __restrict__ enc_attn,
              const float* __restrict__ out) {
    __shared__ float sh[Un];
    const int b   = blockIdx.x;
    const int lc  = blockIdx.y;
    const int tid = threadIdx.x;
    const int lane = tid & 31;
    const int warp = tid >> 5;

    const float4* hb = reinterpret_cast<const float4*>(out + HOUT_OFF + (size_t)b * Un);
    reinterpret_cast<float4*>(sh)[tid]       = hb[tid];
    reinterpret_cast<float4*>(sh)[tid + 256] = hb[tid + 256];
    __syncthreads();

    const float4* sh4 = reinterpret_cast<const float4*>(sh);
    const float* ea = enc_attn + (size_t)b * Ln * Un;
#pragma unroll 1
    for (int i = 0; i < 16; ++i) {
        int l = lc * 128 + warp * 16 + i;
        const float4* row = reinterpret_cast<const float4*>(ea + (size_t)l * Un);
        float s = 0.0f;
#pragma unroll 4
        for (int it = lane; it < Un / 4; it += 32) {
            float4 v = row[it];
            float4 hv = sh4[it];
            s += v.x * hv.x + v.y * hv.y + v.z * hv.z + v.w * hv.w;
        }
#pragma unroll
        for (int o = 16; o > 0; o >>= 1)
            s += __shfl_xor_sync(0xffffffffu, s, o);
        if (lane == 0) g_score[b * Ln + l] = s;
    }
}

// ---------------------------------------------------------------------------
// 4b) Softmax
// ---------------------------------------------------------------------------
__global__ void __launch_bounds__(512)
softmax_kernel() {
    __shared__ float red[16];
    __shared__ float red1;
    const int b = blockIdx.x;
    const int tid = threadIdx.x;
    const int lane = tid & 31;
    const int warp = tid >> 5;

    float v = g_score[b * Ln + tid];
    float m = v;
#pragma unroll
    for (int o = 16; o > 0; o >>= 1)
        m = fmaxf(m, __shfl_xor_sync(0xffffffffu, m, o));
    if (lane == 0) red[warp] = m;
    __syncthreads();
    if (tid == 0) {
        float mm = red[0];
#pragma unroll
        for (int i = 1; i < 16; ++i) mm = fmaxf(mm, red[i]);
        red1 = mm;
    }
    __syncthreads();
    float e = expf(v - red1);
    float s = e;
#pragma unroll
    for (int o = 16; o > 0; o >>= 1)
        s += __shfl_xor_sync(0xffffffffu, s, o);
    if (lane == 0) red[warp] = s;
    __syncthreads();
    if (tid == 0) {
        float ss = 0.0f;
#pragma unroll
        for (int i = 0; i < 16; ++i) ss += red[i];
        red1 = ss;
    }
    __syncthreads();
    g_score[b * Ln + tid] = e / red1;
}

// ---------------------------------------------------------------------------
// 4c) Weighted sum
// ---------------------------------------------------------------------------
__global__ void __launch_bounds__(128)
ctx_kernel(const float* __restrict__ enc_out,
           float* __restrict__ out) {
    __shared__ float w[Ln];
    const int b   = blockIdx.x;
    const int uc  = blockIdx.y;
    const int tid = threadIdx.x;

    reinterpret_cast<float4*>(w)[tid] =
        reinterpret_cast<const float4*>(g_score + (size_t)b * Ln)[tid];
    __syncthreads();

    const float* eo = enc_out + (size_t)b * Ln * Un + uc * 512 + tid * 4;
    float4 acc = make_float4(0.f, 0.f, 0.f, 0.f);
#pragma unroll 4
    for (int l = 0; l < Ln; ++l) {
        float ww = w[l];
        float4 vv = *reinterpret_cast<const float4*>(eo + (size_t)l * Un);
        acc.x = fmaf(ww, vv.x, acc.x);
        acc.y = fmaf(ww, vv.y, acc.y);
        acc.z = fmaf(ww, vv.z, acc.z);
        acc.w = fmaf(ww, vv.w, acc.w);
    }
    *reinterpret_cast<float4*>(out + CTX_OFF + (size_t)b * Un + uc * 512 + tid * 4) = acc;
}

// ---------------------------------------------------------------------------
extern "C" void kernel_launch(void* const* d_in, const int* in_sizes, int n_in,
                              void* d_out, int out_size) {
    const float* x        = (const float*)d_in[0];
    const float* h        = (const float*)d_in[1];
    const float* c        = (const float*)d_in[2];
    const float* context  = (const float*)d_in[3];
    const float* W        = (const float*)d_in[4];
    const float* enc_attn = (const float*)d_in[5];
    const float* enc_out  = (const float*)d_in[6];
    float* out = (float*)d_out;

    cudaFuncSetAttribute(gemm_fp16_kernel,
                         cudaFuncAttributeMaxDynamicSharedMemorySize, GSMEM);

    pack_xh_kernel<<<(Bn * KD + 255) / 256, 256>>>(x, h, context);
    gemm_fp16_kernel<<<OW / BNC, 512, GSMEM>>>(W);
    gates_kernel<<<(Bn * Un + 255) / 256, 256>>>(c, context, out);
    scores_kernel<<<dim3(Bn, 4), 256>>>(enc_attn, out);
    softmax_kernel<<<Bn, 512>>>();
    ctx_kernel<<<dim3(Bn, 4), 128>>>(enc_out, out);
}

// round 17
// speedup vs baseline: 1.3109x; 1.0190x over previous
#include <cuda_runtime.h>
#include <cuda_fp16.h>
#include <math.h>
#include <stdint.h>

// Problem constants
#define Bn   128
#define Un   2048
#define Kn   2
#define Nn   4
#define Ln   512
#define UK   (Un / Kn)        // 1024
#define UN   (Un / Nn)        // 512
#define XHW  (3 * UK)         // 3072
#define KD   (Kn * XHW)       // 6144
#define OW   (4 * Un)         // 8192
#define NW   (4 * UN)         // 2048

// Output layout
#define XOUT_OFF 0
#define HOUT_OFF (Bn * 2 * Un)
#define COUT_OFF (Bn * 3 * Un)
#define CTX_OFF  (Bn * 4 * Un)

// Scratch
__device__ __half g_xh_hi[Bn * KD];       // fp16 A
__device__ float g_part[Bn * OW];         // ifgo
__device__ float g_score[Bn * Ln];        // raw scores

__device__ __forceinline__ float sigmoidf(float v) {
    return 1.0f / (1.0f + expf(-v));
}

__device__ __forceinline__ uint32_t smem_u32(const void* p) {
    uint32_t a;
    asm("{ .reg .u64 t; cvta.to.shared.u64 t, %1; cvt.u32.u64 %0, t; }"
        : "=r"(a) : "l"(p));
    return a;
}

#define CP16(dst, src) \
    asm volatile("cp.async.cg.shared.global [%0], [%1], 16;" \
        :: "r"(dst), "l"(src))
#define CP_COMMIT() asm volatile("cp.async.commit_group;" ::: "memory")
#define CP_WAIT2()  asm volatile("cp.async.wait_group 2;" ::: "memory")
#define CP_WAIT1()  asm volatile("cp.async.wait_group 1;" ::: "memory")
#define CP_WAIT0()  asm volatile("cp.async.wait_group 0;" ::: "memory")

#define LDSM(r, a) \
    asm volatile("ldmatrix.sync.aligned.m8n8.x4.shared.b16 {%0,%1,%2,%3}, [%4];" \
        : "=r"((r)[0]), "=r"((r)[1]), "=r"((r)[2]), "=r"((r)[3]) : "r"(a))
#define LDSM_T(r, a) \
    asm volatile("ldmatrix.sync.aligned.m8n8.x4.trans.shared.b16 {%0,%1,%2,%3}, [%4];" \
        : "=r"((r)[0]), "=r"((r)[1]), "=r"((r)[2]), "=r"((r)[3]) : "r"(a))

__device__ __forceinline__ void mma_fp16(float* d, const uint32_t* a,
                                         uint32_t b0, uint32_t b1) {
    asm volatile(
        "mma.sync.aligned.m16n8k16.row.col.f32.f16.f16.f32 "
        "{%0,%1,%2,%3}, {%4,%5,%6,%7}, {%8,%9}, {%0,%1,%2,%3};\n"
        : "+f"(d[0]), "+f"(d[1]), "+f"(d[2]), "+f"(d[3])
        : "r"(a[0]), "r"(a[1]), "r"(a[2]), "r"(a[3]), "r"(b0), "r"(b1));
}

__device__ __forceinline__ uint32_t pack_h2(__half a, __half b) {
    uint32_t p;
    asm("mov.b32 %0, {%1, %2};" : "=r"(p)
        : "h"(__half_as_ushort(a)), "h"(__half_as_ushort(b)));
    return p;
}

// ---------------------------------------------------------------------------
// 1) Pack XH as fp16
// ---------------------------------------------------------------------------
__global__ void pack_xh_kernel(const float* __restrict__ x,
                               const float* __restrict__ h,
                               const float* __restrict__ ctx) {
    int idx = blockIdx.x * blockDim.x + threadIdx.x;
    if (idx >= Bn * KD) return;
    int b  = idx / KD;
    int kd = idx - b * KD;
    int k  = kd / XHW;
    int d  = kd - k * XHW;
    int off = b * Un + k * UK;
    float v;
    if (d < UK)            v = h[off + d];
    else if (d < 2 * UK)   v = x[off + d - UK];
    else                   v = ctx[off + d - 2 * UK];
    g_xh_hi[idx] = __float2half_rn(v);
}

// ---------------------------------------------------------------------------
// 2) fp16 single-term GEMM; BK=64 stages (96 total, halved barrier count).
//    A fp16 + B fp32 via cp.async (4-slot ring, 3 stages in flight);
//    per-stage in-smem B convert into one reused fp16 tile.
//    Per CTA: M=128, N=64, K=6144. 512 threads (16 warps: 8 M x 2 N).
// ---------------------------------------------------------------------------
#define BNC   64
#define BKS   64
#define NST   (KD / BKS)             // 96
#define NBUF  4
#define A_STRIDE 144                 // bytes per A row (64 fp16 + 16 pad)
#define ASZb  (128 * A_STRIDE)       // 18432
#define BF_STRIDE 272                // bytes per B fp32 k-row (64 fp32 + pad)
#define BFSZb (BKS * BF_STRIDE)      // 17408
#define B_STRIDE 144                 // bytes per B fp16 k-row
#define BHSZb (BKS * B_STRIDE)       // 9216
#define ST_AH 0
#define ST_BF ASZb
#define STSZ  (ASZb + BFSZb)         // 35840
#define BF16_OFF (NBUF * STSZ)       // 143360
#define GSMEM (BF16_OFF + BHSZb)     // 152576

__global__ void __launch_bounds__(512, 1)
gemm_fp16_kernel(const float* __restrict__ W) {
    extern __shared__ char smem[];
    const uint32_t sb = smem_u32(smem);
    const int tid  = threadIdx.x;
    const int lane = tid & 31;
    const int warp = tid >> 5;
    const int wm   = warp & 7;        // rows wm*16
    const int wn   = warp >> 3;       // cols wn*32

    const int col0 = blockIdx.x * BNC;
    const int n    = col0 >> 11;
    const int f0   = col0 & (NW - 1);

    float accm[4][4];
#pragma unroll
    for (int j = 0; j < 4; ++j)
#pragma unroll
        for (int q = 0; q < 4; ++q) accm[j][q] = 0.f;

    // A-load: thread -> (row ar, chunks ac & ac+4); 2 CP16
    const int ar = tid >> 2;          // 0..127
    const int ac = tid & 3;           // 0..3
    // B-load/convert: thread -> (k-row br, chunks bc & bc+8); 2 CP16
    const int br = tid >> 3;          // 0..63
    const int bc = tid & 7;           // 0..7

    auto issue = [&](int s) {
        const uint32_t stb = sb + (s & (NBUF - 1)) * STSZ;
        const int k0 = s * BKS;
        const __half* sh = g_xh_hi + (size_t)ar * KD + k0;
        CP16(stb + ST_AH + ar * A_STRIDE + ac * 16,        sh + ac * 8);
        CP16(stb + ST_AH + ar * A_STRIDE + ac * 16 + 64,   sh + ac * 8 + 32);
        const int kc = (k0 >= XHW) ? 1 : 0;
        const int d  = k0 - kc * XHW + br;
        const float* wsrc = W + ((size_t)(kc * Nn + n) * XHW + d) * (size_t)NW + f0;
        CP16(stb + ST_BF + br * BF_STRIDE + bc * 16,       wsrc + bc * 4);
        CP16(stb + ST_BF + br * BF_STRIDE + bc * 16 + 128, wsrc + bc * 4 + 32);
    };

    auto convertB = [&](int s) {
        const char* src = smem + (s & (NBUF - 1)) * STSZ + ST_BF;
#pragma unroll
        for (int half = 0; half < 2; ++half) {
            int fc = bc * 4 + half * 32;      // float col
            float4 v = *reinterpret_cast<const float4*>(src + br * BF_STRIDE + fc * 4);
            *reinterpret_cast<uint2*>(smem + BF16_OFF + br * B_STRIDE + fc * 2) =
                make_uint2(pack_h2(__float2half_rn(v.x), __float2half_rn(v.y)),
                           pack_h2(__float2half_rn(v.z), __float2half_rn(v.w)));
        }
    };

    auto compute = [&](int s) {
        const uint32_t stb = sb + (s & (NBUF - 1)) * STSZ;
        const uint32_t bft = sb + BF16_OFF;
#pragma unroll
        for (int ks = 0; ks < 4; ++ks) {
            uint32_t bh[2][4];
#pragma unroll
            for (int t = 0; t < 2; ++t) {
                uint32_t ba = bft + (ks * 16 + (lane & 15)) * B_STRIDE
                            + (wn * 32 + t * 16) * 2 + (lane >> 4) * 16;
                LDSM_T(bh[t], ba);
            }
            uint32_t ah[4];
            uint32_t aa = stb + ST_AH
                        + (wm * 16 + (lane & 15)) * A_STRIDE
                        + ks * 32 + (lane >> 4) * 16;
            LDSM(ah, aa);
#pragma unroll
            for (int nt = 0; nt < 4; ++nt) {
                int t = nt >> 1, g = (nt & 1) * 2;
                mma_fp16(accm[nt], ah, bh[t][g], bh[t][g + 1]);
            }
        }
    };

    // Prologue: 3 stages in flight
#pragma unroll
    for (int s = 0; s < 3; ++s) { issue(s); CP_COMMIT(); }

    for (int s = 0; s < NST; ++s) {
        if (s < NST - 2)       CP_WAIT2();
        else if (s == NST - 2) CP_WAIT1();
        else                   CP_WAIT0();
        __syncthreads();                       // sync1: data ready + prev compute done
        if (s + 3 < NST) { issue(s + 3); CP_COMMIT(); }
        convertB(s);
        __syncthreads();                       // sync2: fp16 B tile ready
        compute(s);
    }

    // Epilogue
#pragma unroll
    for (int nt = 0; nt < 4; ++nt) {
        int r  = wm * 16 + (lane >> 2);
        int gc = col0 + wn * 32 + nt * 8 + (lane & 3) * 2;
        *reinterpret_cast<float2*>(&g_part[(size_t)r * OW + gc]) =
            make_float2(accm[nt][0], accm[nt][1]);
        *reinterpret_cast<float2*>(&g_part[(size_t)(r + 8) * OW + gc]) =
            make_float2(accm[nt][2], accm[nt][3]);
    }
}

// ---------------------------------------------------------------------------
// 3) Gates + cell update + output concat
// ---------------------------------------------------------------------------
__global__ void gates_kernel(const float* __restrict__ c,
                             const float* __restrict__ ctx,
                             float* __restrict__ out) {
    int idx = blockIdx.x * blockDim.x + threadIdx.x;
    if (idx >= Bn * Un) return;
    int b = idx >> 11;
    int u = idx & (Un - 1);
    int n = u >> 9;
    int j = u & (UN - 1);
    const float* p = g_part + (size_t)b * OW + n * NW + j;
    float iv = sigmoidf(p[0]);
    float fv = sigmoidf(p[512]);
    float gv = tanhf(p[1024]);
    float ov = sigmoidf(p[1536]);
    float cv = c[idx];
    float nc = fv * cv + iv * gv;
    float nh = ov * tanhf(nc);
    out[HOUT_OFF + idx] = nh;
    out[COUT_OFF + idx] = nc;
    out[XOUT_OFF + b * (2 * Un) + u]      = nh;
    out[XOUT_OFF + b * (2 * Un) + Un + u] = ctx[idx];
}

// ---------------------------------------------------------------------------
// 4a) Attention scores (raw, unnormalized)
// ---------------------------------------------------------------------------
__global__ void __launch_bounds__(256)
scores_kernel(const float* __restrict__ enc_attn,
              const float* __restrict__ out) {
    __shared__ float sh[Un];
    const int b   = blockIdx.x;
    const int lc  = blockIdx.y;
    const int tid = threadIdx.x;
    const int lane = tid & 31;
    const int warp = tid >> 5;

    const float4* hb = reinterpret_cast<const float4*>(out + HOUT_OFF + (size_t)b * Un);
    reinterpret_cast<float4*>(sh)[tid]       = hb[tid];
    reinterpret_cast<float4*>(sh)[tid + 256] = hb[tid + 256];
    __syncthreads();

    const float4* sh4 = reinterpret_cast<const float4*>(sh);
    const float* ea = enc_attn + (size_t)b * Ln * Un;
#pragma unroll 1
    for (int i = 0; i < 16; ++i) {
        int l = lc * 128 + warp * 16 + i;
        const float4* row = reinterpret_cast<const float4*>(ea + (size_t)l * Un);
        float s = 0.0f;
#pragma unroll 4
        for (int it = lane; it < Un / 4; it += 32) {
            float4 v = row[it];
            float4 hv = sh4[it];
            s += v.x * hv.x + v.y * hv.y + v.z * hv.z + v.w * hv.w;
        }
#pragma unroll
        for (int o = 16; o > 0; o >>= 1)
            s += __shfl_xor_sync(0xffffffffu, s, o);
        if (lane == 0) g_score[b * Ln + l] = s;
    }
}

// ---------------------------------------------------------------------------
// 4b) Weighted sum with fused softmax (each block normalizes locally)
// ---------------------------------------------------------------------------
__global__ void __launch_bounds__(128)
ctx_kernel(const float* __restrict__ enc_out,
           float* __restrict__ out) {
    __shared__ float w[Ln];
    __shared__ float red[4];
    const int b   = blockIdx.x;
    const int uc  = blockIdx.y;
    const int tid = threadIdx.x;
    const int lane = tid & 31;
    const int warp = tid >> 5;

    // Load raw scores (4 per thread) and softmax them block-locally
    float4 sv = reinterpret_cast<const float4*>(g_score + (size_t)b * Ln)[tid];
    float m = fmaxf(fmaxf(sv.x, sv.y), fmaxf(sv.z, sv.w));
#pragma unroll
    for (int o = 16; o > 0; o >>= 1)
        m = fmaxf(m, __shfl_xor_sync(0xffffffffu, m, o));
    if (lane == 0) red[warp] = m;
    __syncthreads();
    m = fmaxf(fmaxf(red[0], red[1]), fmaxf(red[2], red[3]));
    float e0 = expf(sv.x - m), e1 = expf(sv.y - m);
    float e2 = expf(sv.z - m), e3 = expf(sv.w - m);
    float sum = e0 + e1 + e2 + e3;
#pragma unroll
    for (int o = 16; o > 0; o >>= 1)
        sum += __shfl_xor_sync(0xffffffffu, sum, o);
    __syncthreads();
    if (lane == 0) red[warp] = sum;
    __syncthreads();
    sum = red[0] + red[1] + red[2] + red[3];
    float inv = 1.0f / sum;
    w[tid * 4 + 0] = e0 * inv;
    w[tid * 4 + 1] = e1 * inv;
    w[tid * 4 + 2] = e2 * inv;
    w[tid * 4 + 3] = e3 * inv;
    __syncthreads();

    const float* eo = enc_out + (size_t)b * Ln * Un + uc * 512 + tid * 4;
    float4 acc = make_float4(0.f, 0.f, 0.f, 0.f);
#pragma unroll 4
    for (int l = 0; l < Ln; ++l) {
        float ww = w[l];
        float4 vv = *reinterpret_cast<const float4*>(eo + (size_t)l * Un);
        acc.x = fmaf(ww, vv.x, acc.x);
        acc.y = fmaf(ww, vv.y, acc.y);
        acc.z = fmaf(ww, vv.z, acc.z);
        acc.w = fmaf(ww, vv.w, acc.w);
    }
    *reinterpret_cast<float4*>(out + CTX_OFF + (size_t)b * Un + uc * 512 + tid * 4) = acc;
}

// ---------------------------------------------------------------------------
extern "C" void kernel_launch(void* const* d_in, const int* in_sizes, int n_in,
                              void* d_out, int out_size) {
    const float* x        = (const float*)d_in[0];
    const float* h        = (const float*)d_in[1];
    const float* c        = (const float*)d_in[2];
    const float* context  = (const float*)d_in[3];
    const float* W        = (const float*)d_in[4];
    const float* enc_attn = (const float*)d_in[5];
    const float* enc_out  = (const float*)d_in[6];
    float* out = (float*)d_out;

    cudaFuncSetAttribute(gemm_fp16_kernel,
                         cudaFuncAttributeMaxDynamicSharedMemorySize, GSMEM);

    pack_xh_kernel<<<(Bn * KD + 255) / 256, 256>>>(x, h, context);
    gemm_fp16_kernel<<<OW / BNC, 512, GSMEM>>>(W);
    gates_kernel<<<(Bn * Un + 255) / 256, 256>>>(c, context, out);
    scores_kernel<<<dim3(Bn, 4), 256>>>(enc_attn, out);
    ctx_kernel<<<dim3(Bn, 4), 128>>>(enc_out, out);
}